// round 1
// baseline (speedup 1.0000x reference)
#include <cuda_runtime.h>

#define BB 128
#define CC 1000
#define DD 300
#define LL 40
#define HH 100

typedef unsigned long long ull;

// ---------------- scratch (device globals; no allocation allowed) ------------
__device__ float g_fu[BB * DD];          // final_utt [B,D]
__device__ float g_cand[CC * DD];        // sigmoid(candidate transform) [C,D]
__device__ float g_M1[DD * DD];          // sys_slots^T @ final_utt [D,D]
__device__ float g_mr[CC * DD];          // request gate matrix [C,D]
__device__ float g_mc[CC * DD];          // confirm gate matrix [C,D]
__device__ float g_Pc[CC * BB];          // (slot@confS^T)*(value@confV^T) [C,B]
__device__ float g_y23[2 * CC];          // y2[c], y3[c]
__device__ float g_Wall[6 * 320 * DD];   // repacked conv weights [tap][f(pad320)][d]

// ---------------- helpers ----------------------------------------------------
__device__ __forceinline__ float sigf(float x) {
    return __fdividef(1.f, 1.f + __expf(-x));
}
__device__ __forceinline__ ull ld2(const float* p) {
    return *reinterpret_cast<const ull*>(p);
}
__device__ __forceinline__ float lo2(ull v) { return __int_as_float((unsigned)v); }
__device__ __forceinline__ float hi2(ull v) { return __int_as_float((unsigned)(v >> 32)); }
__device__ __forceinline__ float psum(ull v) { return lo2(v) + hi2(v); }
// packed dual-fp32 FMA (sm_100+): d = a*b + d on both 32-bit halves
__device__ __forceinline__ void fma2(ull& d, ull a, ull b) {
    asm("fma.rn.f32x2 %0, %1, %2, %0;" : "+l"(d) : "l"(a), "l"(b));
}
__device__ __forceinline__ float wredsum(float v) {
    #pragma unroll
    for (int o = 16; o; o >>= 1) v += __shfl_xor_sync(0xffffffffu, v, o);
    return v;
}

// ---------------- 1) repack conv weights into [tap][f pad 320][d] -------------
__global__ void repack_kernel(const float* __restrict__ w1,
                              const float* __restrict__ w2,
                              const float* __restrict__ w3) {
    int idx = blockIdx.x * 256 + threadIdx.x;
    if (idx >= 6 * 320 * DD) return;
    int d = idx % DD;
    int r = idx / DD;
    int f = r % 320;
    int tap = r / 320;
    float v = 0.f;
    if (f < DD) {
        int base = f * DD + d;
        switch (tap) {
            case 0: v = w1[base];         break;  // w1[f][d][0]
            case 1: v = w2[base * 2];     break;  // w2[f][d][0]
            case 2: v = w2[base * 2 + 1]; break;  // w2[f][d][1]
            case 3: v = w3[base * 3];     break;  // w3[f][d][0]
            case 4: v = w3[base * 3 + 1]; break;  // w3[f][d][1]
            case 5: v = w3[base * 3 + 2]; break;  // w3[f][d][2]
        }
    }
    g_Wall[(tap * 320 + f) * DD + d] = v;
}

// ---------------- 2) CNN encoder: final_utt[b,f] ------------------------------
// GEMM per (b, 32-filter group): G[tap][l][f] = sum_d x[l,d]*w[tap,f,d],
// then combine taps with shifted l and relu+max over time.
__global__ void conv_kernel(const float* __restrict__ utt,
                            const float* __restrict__ cb1,
                            const float* __restrict__ cb2,
                            const float* __restrict__ cb3) {
    __shared__ float Xs[40][32];
    __shared__ float SH[7680];                       // Ws[192][32] then Gs[6][40][32]
    float (*Ws)[32] = (float(*)[32])SH;
    float (*Gs)[40][32] = (float(*)[40][32])SH;

    int t = threadIdx.x;
    int tx = t & 31, ty = t >> 5;
    int f0 = blockIdx.x * 32;
    int b  = blockIdx.y;

    ull acc[5][6];
    #pragma unroll
    for (int j = 0; j < 5; j++)
        #pragma unroll
        for (int k = 0; k < 6; k++) acc[j][k] = 0ull;

    for (int d0 = 0; d0 < DD; d0 += 32) {
        __syncthreads();
        #pragma unroll
        for (int i = 0; i < 5; i++) {              // 40x32 X tile
            int idx = t + i * 256;
            int l = idx >> 5, dd = idx & 31;
            int d = d0 + dd;
            Xs[l][dd] = (d < DD) ? utt[b * (LL * DD) + l * DD + d] : 0.f;
        }
        #pragma unroll
        for (int i = 0; i < 24; i++) {             // 192x32 W tile
            int idx = t + i * 256;
            int col = idx >> 5, dd = idx & 31;
            int tap = col >> 5, fl = col & 31;
            int d = d0 + dd;
            Ws[col][dd] = (d < DD) ? g_Wall[(tap * 320 + f0 + fl) * DD + d] : 0.f;
        }
        __syncthreads();
        #pragma unroll
        for (int p = 0; p < 16; p++) {
            ull a2[5], w2[6];
            #pragma unroll
            for (int j = 0; j < 5; j++) a2[j] = ld2(&Xs[ty + 8 * j][2 * p]);
            #pragma unroll
            for (int k = 0; k < 6; k++) w2[k] = ld2(&Ws[tx + 32 * k][2 * p]);
            #pragma unroll
            for (int j = 0; j < 5; j++)
                #pragma unroll
                for (int k = 0; k < 6; k++) fma2(acc[j][k], a2[j], w2[k]);
        }
    }
    __syncthreads();
    #pragma unroll
    for (int j = 0; j < 5; j++)
        #pragma unroll
        for (int k = 0; k < 6; k++) Gs[k][ty + 8 * j][tx] = psum(acc[j][k]);
    __syncthreads();

    if (t < 32) {
        int f = f0 + t;
        if (f < DD) {
            float z1 = -1e30f, z2 = -1e30f, z3 = -1e30f;
            #pragma unroll
            for (int l = 0; l < 40; l++) z1 = fmaxf(z1, Gs[0][l][t]);
            #pragma unroll
            for (int l = 0; l < 39; l++) z2 = fmaxf(z2, Gs[1][l][t] + Gs[2][l + 1][t]);
            #pragma unroll
            for (int l = 0; l < 38; l++) z3 = fmaxf(z3, Gs[3][l][t] + Gs[4][l + 1][t] + Gs[5][l + 2][t]);
            g_fu[b * DD + f] = fmaxf(z1 + cb1[f], 0.f) + fmaxf(z2 + cb2[f], 0.f) + fmaxf(z3 + cb3[f], 0.f);
        }
    }
}

// ---------------- 3) candidate transform: g_cand = sigmoid([slot,value]@Wc^T+bc)
__global__ void cand_kernel(const float* __restrict__ slot,
                            const float* __restrict__ val,
                            const float* __restrict__ Wc,
                            const float* __restrict__ bc) {
    __shared__ float As[16][32];
    __shared__ float Ws[128][32];
    int t = threadIdx.x, tx = t & 31, ty = t >> 5;
    int c0 = blockIdx.x * 16, j0 = blockIdx.y * 128;

    ull acc[2][4];
    #pragma unroll
    for (int m = 0; m < 2; m++)
        #pragma unroll
        for (int k = 0; k < 4; k++) acc[m][k] = 0ull;

    for (int k0 = 0; k0 < 600; k0 += 32) {
        __syncthreads();
        #pragma unroll
        for (int i = 0; i < 2; i++) {
            int idx = t + i * 256;
            int row = idx >> 5, kk = idx & 31;
            int c = c0 + row, k = k0 + kk;
            float v = 0.f;
            if (c < CC && k < 600) v = (k < DD) ? slot[c * DD + k] : val[c * DD + k - DD];
            As[row][kk] = v;
        }
        #pragma unroll
        for (int i = 0; i < 16; i++) {
            int idx = t + i * 256;
            int jj = idx >> 5, kk = idx & 31;
            int j = j0 + jj, k = k0 + kk;
            Ws[jj][kk] = (j < DD && k < 600) ? Wc[j * 600 + k] : 0.f;
        }
        __syncthreads();
        #pragma unroll
        for (int p = 0; p < 16; p++) {
            ull a2[2], w2[4];
            #pragma unroll
            for (int m = 0; m < 2; m++) a2[m] = ld2(&As[ty + 8 * m][2 * p]);
            #pragma unroll
            for (int k = 0; k < 4; k++) w2[k] = ld2(&Ws[tx + 32 * k][2 * p]);
            #pragma unroll
            for (int m = 0; m < 2; m++)
                #pragma unroll
                for (int k = 0; k < 4; k++) fma2(acc[m][k], a2[m], w2[k]);
        }
    }
    #pragma unroll
    for (int m = 0; m < 2; m++)
        #pragma unroll
        for (int k = 0; k < 4; k++) {
            int c = c0 + ty + 8 * m;
            int j = j0 + tx + 32 * k;
            if (c < CC && j < DD) g_cand[c * DD + j] = sigf(psum(acc[m][k]) + bc[j]);
        }
}

// ---------------- 4) M1 = sys_slots^T @ final_utt [D,D] ------------------------
__global__ void m1_kernel(const float* __restrict__ sys) {
    int j = blockIdx.x * 128 + threadIdx.x;
    int i0 = blockIdx.y * 4;
    if (j >= DD) return;
    float acc[4] = {0.f, 0.f, 0.f, 0.f};
    for (int b = 0; b < BB; b++) {
        float fv = g_fu[b * DD + j];
        #pragma unroll
        for (int ii = 0; ii < 4; ii++) acc[ii] += sys[b * DD + i0 + ii] * fv;
    }
    #pragma unroll
    for (int ii = 0; ii < 4; ii++) g_M1[(i0 + ii) * DD + j] = acc[ii];
}

// ---------------- 5) P_c[c,b] = (slot[c]·confS[b]) * (value[c]·confV[b]) -------
__global__ void pc_kernel(const float* __restrict__ slot,
                          const float* __restrict__ val,
                          const float* __restrict__ cs,
                          const float* __restrict__ cv) {
    __shared__ float Ss[64][32], Ve[64][32], Cs[64][32], Cv[64][32];
    int t = threadIdx.x, tx = t & 31, ty = t >> 5;
    int c0 = blockIdx.x * 64, b0 = blockIdx.y * 64;

    ull accA[8][2], accB[8][2];
    #pragma unroll
    for (int m = 0; m < 8; m++)
        #pragma unroll
        for (int k = 0; k < 2; k++) { accA[m][k] = 0ull; accB[m][k] = 0ull; }

    for (int d0 = 0; d0 < DD; d0 += 32) {
        __syncthreads();
        #pragma unroll
        for (int i = 0; i < 8; i++) {
            int idx = t + i * 256;
            int row = idx >> 5, dd = idx & 31;
            int d = d0 + dd;
            int c = c0 + row;
            bool okc = (c < CC && d < DD);
            Ss[row][dd] = okc ? slot[c * DD + d] : 0.f;
            Ve[row][dd] = okc ? val[c * DD + d] : 0.f;
            bool okb = (d < DD);
            Cs[row][dd] = okb ? cs[(b0 + row) * DD + d] : 0.f;
            Cv[row][dd] = okb ? cv[(b0 + row) * DD + d] : 0.f;
        }
        __syncthreads();
        #pragma unroll
        for (int p = 0; p < 16; p++) {
            ull aS[8], aV[8], wC[2], wV[2];
            #pragma unroll
            for (int m = 0; m < 8; m++) {
                aS[m] = ld2(&Ss[ty + 8 * m][2 * p]);
                aV[m] = ld2(&Ve[ty + 8 * m][2 * p]);
            }
            #pragma unroll
            for (int k = 0; k < 2; k++) {
                wC[k] = ld2(&Cs[tx + 32 * k][2 * p]);
                wV[k] = ld2(&Cv[tx + 32 * k][2 * p]);
            }
            #pragma unroll
            for (int m = 0; m < 8; m++)
                #pragma unroll
                for (int k = 0; k < 2; k++) {
                    fma2(accA[m][k], aS[m], wC[k]);
                    fma2(accB[m][k], aV[m], wV[k]);
                }
        }
    }
    #pragma unroll
    for (int m = 0; m < 8; m++)
        #pragma unroll
        for (int k = 0; k < 2; k++) {
            int c = c0 + ty + 8 * m;
            int b = b0 + tx + 32 * k;
            if (c < CC) g_Pc[c * BB + b] = psum(accA[m][k]) * psum(accB[m][k]);
        }
}

// ---------------- 6) generic A[M,K] @ B[K,300] (mode 0: m_r, mode 1: m_c) ------
__global__ void gemm_rn_kernel(const float* __restrict__ slotp, int mode) {
    const float* A  = mode ? g_Pc : slotp;
    const float* Bm = mode ? g_fu : g_M1;
    float* Out      = mode ? g_mc : g_mr;
    int K           = mode ? BB : DD;

    __shared__ float As[64][32];
    __shared__ float Bs[128][34];
    int t = threadIdx.x, tx = t & 31, ty = t >> 5;
    int m0 = blockIdx.x * 64, n0 = blockIdx.y * 128;

    ull acc[8][4];
    #pragma unroll
    for (int m = 0; m < 8; m++)
        #pragma unroll
        for (int k = 0; k < 4; k++) acc[m][k] = 0ull;

    int nch = (K + 31) >> 5;
    for (int ch = 0; ch < nch; ch++) {
        int k0 = ch * 32;
        __syncthreads();
        #pragma unroll
        for (int i = 0; i < 8; i++) {
            int idx = t + i * 256;
            int row = idx >> 5, kk = idx & 31;
            int m = m0 + row, k = k0 + kk;
            As[row][kk] = (m < CC && k < K) ? A[m * K + k] : 0.f;
        }
        #pragma unroll
        for (int i = 0; i < 16; i++) {
            int idx = t + i * 256;
            int nn = idx & 127, kk = idx >> 7;
            int n = n0 + nn, k = k0 + kk;
            Bs[nn][kk] = (k < K && n < DD) ? Bm[k * DD + n] : 0.f;
        }
        __syncthreads();
        #pragma unroll
        for (int p = 0; p < 16; p++) {
            ull a2[8], w2[4];
            #pragma unroll
            for (int m = 0; m < 8; m++) a2[m] = ld2(&As[ty + 8 * m][2 * p]);
            #pragma unroll
            for (int k = 0; k < 4; k++) w2[k] = ld2(&Bs[tx + 32 * k][2 * p]);
            #pragma unroll
            for (int m = 0; m < 8; m++)
                #pragma unroll
                for (int k = 0; k < 4; k++) fma2(acc[m][k], a2[m], w2[k]);
        }
    }
    #pragma unroll
    for (int m = 0; m < 8; m++)
        #pragma unroll
        for (int k = 0; k < 4; k++) {
            int mm = m0 + ty + 8 * m;
            int n = n0 + tx + 32 * k;
            if (mm < CC && n < DD) Out[mm * DD + n] = psum(acc[m][k]);
        }
}

// ---------------- 7) y2/y3: y[c] = Wj . sigmoid(Wm @ sigmoid(m[c,:]) + bm) + bj
__global__ void y23_kernel(const float* __restrict__ Wmr, const float* __restrict__ bmr,
                           const float* __restrict__ Wmc, const float* __restrict__ bmc,
                           const float* __restrict__ Wj,  const float* __restrict__ bj) {
    int which = blockIdx.y;
    const float* Min = which ? g_mc : g_mr;
    const float* Wm  = which ? Wmc : Wmr;
    const float* bm  = which ? bmc : bmr;

    __shared__ float As[32][32], Ws[128][32], bmS[128], WjS[128];
    int t = threadIdx.x, tx = t & 31, ty = t >> 5;
    int c0 = blockIdx.x * 32;
    if (t < 128) {
        bmS[t] = (t < HH) ? bm[t] : 0.f;
        WjS[t] = (t < HH) ? Wj[t] : 0.f;
    }

    ull acc[4][4];
    #pragma unroll
    for (int m = 0; m < 4; m++)
        #pragma unroll
        for (int k = 0; k < 4; k++) acc[m][k] = 0ull;

    for (int d0 = 0; d0 < DD; d0 += 32) {
        __syncthreads();
        #pragma unroll
        for (int i = 0; i < 4; i++) {
            int idx = t + i * 256;
            int row = idx >> 5, dd = idx & 31;
            int c = c0 + row, d = d0 + dd;
            As[row][dd] = (c < CC && d < DD) ? sigf(Min[c * DD + d]) : 0.f;
        }
        #pragma unroll
        for (int i = 0; i < 16; i++) {
            int idx = t + i * 256;
            int h = idx >> 5, dd = idx & 31;
            int d = d0 + dd;
            Ws[h][dd] = (h < HH && d < DD) ? Wm[h * DD + d] : 0.f;
        }
        __syncthreads();
        #pragma unroll
        for (int p = 0; p < 16; p++) {
            ull a2[4], w2[4];
            #pragma unroll
            for (int m = 0; m < 4; m++) a2[m] = ld2(&As[ty + 8 * m][2 * p]);
            #pragma unroll
            for (int k = 0; k < 4; k++) w2[k] = ld2(&Ws[tx + 32 * k][2 * p]);
            #pragma unroll
            for (int m = 0; m < 4; m++)
                #pragma unroll
                for (int k = 0; k < 4; k++) fma2(acc[m][k], a2[m], w2[k]);
        }
    }
    float bjv = bj[0];
    #pragma unroll
    for (int m = 0; m < 4; m++) {
        float pv = 0.f;
        #pragma unroll
        for (int k = 0; k < 4; k++) {
            int h = tx + 32 * k;
            float hid = psum(acc[m][k]) + bmS[h];
            pv += sigf(hid) * WjS[h];          // WjS==0 for padded h -> no contribution
        }
        pv = wredsum(pv);
        if (tx == 0) {
            int c = c0 + ty + 8 * m;
            if (c < CC) g_y23[which * CC + c] = pv + bjv;
        }
    }
}

// ---------------- 8) fused main: per (b, c-tile 64) ----------------------------
// hidden[c,h] = sum_d sigmoid(cand[c,d]*fu[b,d]) * Wd[h,d] + bd[h]
// y1 = Wj . sigmoid(hidden) + bj; out = 0.5*(y1+y2+y3) + 0.5*y_past
__global__ void main_kernel(const float* __restrict__ Wd, const float* __restrict__ bd,
                            const float* __restrict__ Wj, const float* __restrict__ bj,
                            const float* __restrict__ ypast, float* __restrict__ out) {
    __shared__ float fuS[304];
    __shared__ float As[64][32];
    __shared__ float Ws[128][32];
    __shared__ float bdS[128], WjS[128];

    int t = threadIdx.x, tx = t & 31, ty = t >> 5;
    int c0 = blockIdx.x * 64;
    int b  = blockIdx.y;

    if (t < 128) {
        bdS[t] = (t < HH) ? bd[t] : 0.f;
        WjS[t] = (t < HH) ? Wj[t] : 0.f;
    }
    for (int i = t; i < DD; i += 256) fuS[i] = g_fu[b * DD + i];

    ull acc[8][4];
    #pragma unroll
    for (int m = 0; m < 8; m++)
        #pragma unroll
        for (int k = 0; k < 4; k++) acc[m][k] = 0ull;

    for (int d0 = 0; d0 < DD; d0 += 32) {
        __syncthreads();
        #pragma unroll
        for (int i = 0; i < 8; i++) {
            int idx = t + i * 256;
            int row = idx >> 5, dd = idx & 31;
            int c = c0 + row, d = d0 + dd;
            float v = 0.f;
            if (c < CC && d < DD) v = sigf(g_cand[c * DD + d] * fuS[d]);
            As[row][dd] = v;
        }
        #pragma unroll
        for (int i = 0; i < 16; i++) {
            int idx = t + i * 256;
            int h = idx >> 5, dd = idx & 31;
            int d = d0 + dd;
            Ws[h][dd] = (h < HH && d < DD) ? Wd[h * DD + d] : 0.f;
        }
        __syncthreads();
        #pragma unroll
        for (int p = 0; p < 16; p++) {
            ull a2[8], w2[4];
            #pragma unroll
            for (int m = 0; m < 8; m++) a2[m] = ld2(&As[ty + 8 * m][2 * p]);
            #pragma unroll
            for (int k = 0; k < 4; k++) w2[k] = ld2(&Ws[tx + 32 * k][2 * p]);
            #pragma unroll
            for (int m = 0; m < 8; m++)
                #pragma unroll
                for (int k = 0; k < 4; k++) fma2(acc[m][k], a2[m], w2[k]);
        }
    }

    float bjv = bj[0];
    #pragma unroll
    for (int m = 0; m < 8; m++) {
        float pv = 0.f;
        #pragma unroll
        for (int k = 0; k < 4; k++) {
            int h = tx + 32 * k;
            float hid = psum(acc[m][k]) + bdS[h];
            pv += sigf(hid) * WjS[h];
        }
        pv = wredsum(pv);
        if (tx == 0) {
            int c = c0 + ty + 8 * m;
            if (c < CC) {
                float y1 = pv + bjv;
                float v = 0.5f * (y1 + g_y23[c] + g_y23[CC + c]) + 0.5f * ypast[b * CC + c];
                out[b * CC + c] = v;
            }
        }
    }
}

// ---------------- launch ------------------------------------------------------
extern "C" void kernel_launch(void* const* d_in, const int* in_sizes, int n_in,
                              void* d_out, int out_size) {
    const float* utt   = (const float*)d_in[0];
    const float* sys   = (const float*)d_in[1];
    const float* cs    = (const float*)d_in[2];
    const float* cv    = (const float*)d_in[3];
    const float* ypast = (const float*)d_in[4];
    const float* slot  = (const float*)d_in[5];
    const float* val   = (const float*)d_in[6];
    const float* Wc    = (const float*)d_in[7];
    const float* bc    = (const float*)d_in[8];
    const float* w1    = (const float*)d_in[9];
    const float* b1    = (const float*)d_in[10];
    const float* w2    = (const float*)d_in[11];
    const float* b2    = (const float*)d_in[12];
    const float* w3    = (const float*)d_in[13];
    const float* b3    = (const float*)d_in[14];
    const float* Wd    = (const float*)d_in[15];
    const float* bd    = (const float*)d_in[16];
    const float* Wmr   = (const float*)d_in[17];
    const float* bmr   = (const float*)d_in[18];
    const float* Wmc   = (const float*)d_in[19];
    const float* bmc   = (const float*)d_in[20];
    const float* Wj    = (const float*)d_in[21];
    const float* bj    = (const float*)d_in[22];
    float* out = (float*)d_out;

    repack_kernel<<<(6 * 320 * DD + 255) / 256, 256>>>(w1, w2, w3);
    conv_kernel<<<dim3(10, BB), 256>>>(utt, b1, b2, b3);
    cand_kernel<<<dim3(63, 3), 256>>>(slot, val, Wc, bc);
    m1_kernel<<<dim3(3, 75), 128>>>(sys);
    pc_kernel<<<dim3(16, 2), 256>>>(slot, val, cs, cv);
    gemm_rn_kernel<<<dim3(16, 3), 256>>>(slot, 0);  // m_r = slot @ M1
    gemm_rn_kernel<<<dim3(16, 3), 256>>>(slot, 1);  // m_c = P_c @ fu
    y23_kernel<<<dim3(32, 2), 256>>>(Wmr, bmr, Wmc, bmc, Wj, bj);
    main_kernel<<<dim3(16, BB), 256>>>(Wd, bd, Wj, bj, ypast, out);
}

// round 2
// speedup vs baseline: 4.6561x; 4.6561x over previous
#include <cuda_runtime.h>

#define BB 128
#define CC 1000
#define DD 300
#define LL 40
#define HH 100

typedef unsigned long long ull;

// ---------------- scratch (device globals) -----------------------------------
__device__ float g_fu[BB * DD];                 // final_utt [B,D]
__device__ float g_cand_t[DD * CC];             // sigmoid(cand transform) TRANSPOSED [d][c]
__device__ float g_M1[DD * DD];                 // sys_slots^T @ final_utt [D,D]
__device__ float g_mr[CC * DD];                 // request gate matrix [C,D]
__device__ float g_mc[CC * DD];                 // confirm gate matrix [C,D]
__device__ float g_Pc[CC * BB];                 // (slot@confS^T)*(value@confV^T) [C,B]
__device__ float g_y23[2 * CC];                 // y2[c], y3[c]
__device__ float g_Wt_conv[320 * 1920];         // conv weights [d pad320][f*6+tap], f pad320
__device__ ull   g_Wd_dup[320 * 128];           // Wd duplicated pairs [d pad320][h pad128]

// ---------------- helpers ----------------------------------------------------
__device__ __forceinline__ float sigf(float x) {
    return __fdividef(1.f, 1.f + __expf(-x));
}
__device__ __forceinline__ ull ld2(const float* p) {
    return *reinterpret_cast<const ull*>(p);
}
__device__ __forceinline__ float lo2(ull v) { return __int_as_float((unsigned)v); }
__device__ __forceinline__ float hi2(ull v) { return __int_as_float((unsigned)(v >> 32)); }
__device__ __forceinline__ float psum(ull v) { return lo2(v) + hi2(v); }
__device__ __forceinline__ void fma2(ull& d, ull a, ull b) {
    asm("fma.rn.f32x2 %0, %1, %2, %0;" : "+l"(d) : "l"(a), "l"(b));
}
__device__ __forceinline__ ull dup2(float x) {
    ull r;
    asm("mov.b64 %0, {%1, %1};" : "=l"(r) : "r"(__float_as_uint(x)));
    return r;
}
__device__ __forceinline__ float wredsum(float v) {
    #pragma unroll
    for (int o = 16; o; o >>= 1) v += __shfl_xor_sync(0xffffffffu, v, o);
    return v;
}

// ---------------- 1) repack: conv weights (transposed), Wd dup, zero M1 -------
#define N_WT  (320 * 1920)
#define N_WD  (320 * 128)
#define N_M1  (DD * DD)
__global__ void repack_kernel(const float* __restrict__ w1,
                              const float* __restrict__ w2,
                              const float* __restrict__ w3,
                              const float* __restrict__ Wd) {
    int idx = blockIdx.x * 256 + threadIdx.x;
    if (idx < N_WT) {
        int dp  = idx / 1920;
        int col = idx % 1920;
        int f   = col / 6;
        int tap = col % 6;
        float v = 0.f;
        if (dp < DD && f < DD) {
            int base = f * DD + dp;
            switch (tap) {
                case 0: v = w1[base];         break;
                case 1: v = w2[base * 2];     break;
                case 2: v = w2[base * 2 + 1]; break;
                case 3: v = w3[base * 3];     break;
                case 4: v = w3[base * 3 + 1]; break;
                case 5: v = w3[base * 3 + 2]; break;
            }
        }
        g_Wt_conv[idx] = v;
    } else if (idx < N_WT + N_WD) {
        int i2 = idx - N_WT;
        int dp = i2 / 128, h = i2 % 128;
        float v = (dp < DD && h < HH) ? Wd[h * DD + dp] : 0.f;
        g_Wd_dup[i2] = dup2(v);
    } else if (idx < N_WT + N_WD + N_M1) {
        g_M1[idx - N_WT - N_WD] = 0.f;
    }
}

// ---------------- 2) CNN encoder (GEMM over [l,40] x [F'=f*6+tap,384-tile]) ---
// n-pair scheme: each lane's f32x2 holds two adjacent F' columns.
__global__ void __launch_bounds__(256) conv_kernel(
        const float* __restrict__ utt,
        const float* __restrict__ cb1,
        const float* __restrict__ cb2,
        const float* __restrict__ cb3) {
    __shared__ __align__(16) ull  Xd[40][16];     // dup x pairs [l][kk]
    __shared__ __align__(16) float WG[8000];      // Ws[16][384] (MMA) then Gs[40][200] (epi)

    int t = threadIdx.x, tx = t & 31, ty = t >> 5;
    int fg = blockIdx.x;          // f-group: 64 filters = 384 F'-cols
    int b  = blockIdx.y;

    ull acc[5][6];
    #pragma unroll
    for (int m = 0; m < 5; m++)
        #pragma unroll
        for (int k = 0; k < 6; k++) acc[m][k] = 0ull;

    for (int ch = 0; ch < 19; ch++) {
        int d0 = ch * 16;
        __syncthreads();
        // load W tile: Ws[kk][cc] = Wt[(d0+kk)][fg*384+cc]
        #pragma unroll
        for (int i = 0; i < 24; i++) {
            int idx = t + i * 256;
            int kk = idx / 384, cc = idx % 384;
            WG[kk * 384 + cc] = g_Wt_conv[(d0 + kk) * 1920 + fg * 384 + cc];
        }
        // load X dup tile: Xd[l][kk] = (x,x) with x = utt[b][l][d0+kk]
        #pragma unroll
        for (int i = 0; i < 3; i++) {
            int idx = t + i * 256;
            if (idx < 640) {
                int l = idx >> 4, kk = idx & 15;
                int d = d0 + kk;
                float x = (d < DD) ? utt[b * (LL * DD) + l * DD + d] : 0.f;
                Xd[l][kk] = dup2(x);
            }
        }
        __syncthreads();
        #pragma unroll
        for (int kk = 0; kk < 16; kk++) {
            ull b2[6];
            #pragma unroll
            for (int k = 0; k < 6; k++) b2[k] = ld2(&WG[kk * 384 + 2 * tx + 64 * k]);
            #pragma unroll
            for (int m = 0; m < 5; m++) {
                ull a2 = Xd[5 * ty + m][kk];
                #pragma unroll
                for (int k = 0; k < 6; k++) fma2(acc[m][k], a2, b2[k]);
            }
        }
    }

    // epilogue: two phases of 32 filters each (reuse WG as Gs[40][200])
    #pragma unroll
    for (int ph = 0; ph < 2; ph++) {
        __syncthreads();
        #pragma unroll
        for (int m = 0; m < 5; m++)
            #pragma unroll
            for (int k = 0; k < 3; k++) {
                int kc = 3 * ph + k;
                int col = 2 * tx + 64 * kc - ph * 192;
                *reinterpret_cast<ull*>(&WG[(5 * ty + m) * 200 + col]) = acc[m][kc];
            }
        __syncthreads();
        if (t < 32) {
            int f = fg * 64 + ph * 32 + t;
            if (f < DD) {
                float z1 = -1e30f, z2 = -1e30f, z3 = -1e30f;
                #pragma unroll
                for (int l = 0; l < 40; l++) z1 = fmaxf(z1, WG[l * 200 + t * 6 + 0]);
                #pragma unroll
                for (int l = 0; l < 39; l++)
                    z2 = fmaxf(z2, WG[l * 200 + t * 6 + 1] + WG[(l + 1) * 200 + t * 6 + 2]);
                #pragma unroll
                for (int l = 0; l < 38; l++)
                    z3 = fmaxf(z3, WG[l * 200 + t * 6 + 3] + WG[(l + 1) * 200 + t * 6 + 4]
                                   + WG[(l + 2) * 200 + t * 6 + 5]);
                g_fu[b * DD + f] = fmaxf(z1 + cb1[f], 0.f) + fmaxf(z2 + cb2[f], 0.f)
                                 + fmaxf(z3 + cb3[f], 0.f);
            }
        }
    }
}

// ---------------- 3) candidate transform -> TRANSPOSED output -----------------
__global__ void cand_kernel(const float* __restrict__ slot,
                            const float* __restrict__ val,
                            const float* __restrict__ Wc,
                            const float* __restrict__ bc) {
    __shared__ __align__(8) float As[16][32];
    __shared__ __align__(8) float Ws[128][34];
    int t = threadIdx.x, tx = t & 31, ty = t >> 5;
    int c0 = blockIdx.x * 16, j0 = blockIdx.y * 128;

    ull acc[2][4];
    #pragma unroll
    for (int m = 0; m < 2; m++)
        #pragma unroll
        for (int k = 0; k < 4; k++) acc[m][k] = 0ull;

    for (int k0 = 0; k0 < 600; k0 += 32) {
        __syncthreads();
        #pragma unroll
        for (int i = 0; i < 2; i++) {
            int idx = t + i * 256;
            int row = idx >> 5, kk = idx & 31;
            int c = c0 + row, k = k0 + kk;
            float v = 0.f;
            if (c < CC) v = (k < DD) ? slot[c * DD + k] : val[c * DD + k - DD];
            As[row][kk] = v;
        }
        #pragma unroll
        for (int i = 0; i < 16; i++) {
            int idx = t + i * 256;
            int jj = idx >> 5, kk = idx & 31;
            int j = j0 + jj, k = k0 + kk;
            Ws[jj][kk] = (j < DD) ? Wc[j * 600 + k] : 0.f;
        }
        __syncthreads();
        #pragma unroll
        for (int p = 0; p < 16; p++) {
            ull a2[2], w2[4];
            #pragma unroll
            for (int m = 0; m < 2; m++) a2[m] = ld2(&As[ty + 8 * m][2 * p]);
            #pragma unroll
            for (int k = 0; k < 4; k++) w2[k] = ld2(&Ws[tx + 32 * k][2 * p]);
            #pragma unroll
            for (int m = 0; m < 2; m++)
                #pragma unroll
                for (int k = 0; k < 4; k++) fma2(acc[m][k], a2[m], w2[k]);
        }
    }
    #pragma unroll
    for (int m = 0; m < 2; m++)
        #pragma unroll
        for (int k = 0; k < 4; k++) {
            int c = c0 + ty + 8 * m;
            int j = j0 + tx + 32 * k;
            if (c < CC && j < DD)
                g_cand_t[j * CC + c] = sigf(psum(acc[m][k]) + bc[j]);
        }
}

// ---------------- 4) M1 = sys_slots^T @ final_utt [D,D] (b-split + atomics) ---
__global__ void m1_kernel(const float* __restrict__ sys) {
    int j = blockIdx.x * 128 + threadIdx.x;
    int i0 = blockIdx.y * 4;
    int b0 = blockIdx.z * 32;
    if (j >= DD) return;
    float acc[4] = {0.f, 0.f, 0.f, 0.f};
    #pragma unroll 4
    for (int b = b0; b < b0 + 32; b++) {
        float fv = g_fu[b * DD + j];
        #pragma unroll
        for (int ii = 0; ii < 4; ii++) acc[ii] += sys[b * DD + i0 + ii] * fv;
    }
    #pragma unroll
    for (int ii = 0; ii < 4; ii++) atomicAdd(&g_M1[(i0 + ii) * DD + j], acc[ii]);
}

// ---------------- 5) P_c[c,b] -------------------------------------------------
__global__ void pc_kernel(const float* __restrict__ slot,
                          const float* __restrict__ val,
                          const float* __restrict__ cs,
                          const float* __restrict__ cv) {
    __shared__ __align__(8) float Ss[64][32], Ve[64][32];
    __shared__ __align__(8) float Cs[64][34], Cv[64][34];
    int t = threadIdx.x, tx = t & 31, ty = t >> 5;
    int c0 = blockIdx.x * 64, b0 = blockIdx.y * 64;

    ull accA[8][2], accB[8][2];
    #pragma unroll
    for (int m = 0; m < 8; m++)
        #pragma unroll
        for (int k = 0; k < 2; k++) { accA[m][k] = 0ull; accB[m][k] = 0ull; }

    for (int d0 = 0; d0 < DD; d0 += 32) {
        __syncthreads();
        #pragma unroll
        for (int i = 0; i < 8; i++) {
            int idx = t + i * 256;
            int row = idx >> 5, dd = idx & 31;
            int d = d0 + dd;
            int c = c0 + row;
            bool okc = (c < CC && d < DD);
            Ss[row][dd] = okc ? slot[c * DD + d] : 0.f;
            Ve[row][dd] = okc ? val[c * DD + d] : 0.f;
            bool okb = (d < DD);
            Cs[row][dd] = okb ? cs[(b0 + row) * DD + d] : 0.f;
            Cv[row][dd] = okb ? cv[(b0 + row) * DD + d] : 0.f;
        }
        __syncthreads();
        #pragma unroll
        for (int p = 0; p < 16; p++) {
            ull aS[8], aV[8], wC[2], wV[2];
            #pragma unroll
            for (int m = 0; m < 8; m++) {
                aS[m] = ld2(&Ss[ty + 8 * m][2 * p]);
                aV[m] = ld2(&Ve[ty + 8 * m][2 * p]);
            }
            #pragma unroll
            for (int k = 0; k < 2; k++) {
                wC[k] = ld2(&Cs[tx + 32 * k][2 * p]);
                wV[k] = ld2(&Cv[tx + 32 * k][2 * p]);
            }
            #pragma unroll
            for (int m = 0; m < 8; m++)
                #pragma unroll
                for (int k = 0; k < 2; k++) {
                    fma2(accA[m][k], aS[m], wC[k]);
                    fma2(accB[m][k], aV[m], wV[k]);
                }
        }
    }
    #pragma unroll
    for (int m = 0; m < 8; m++)
        #pragma unroll
        for (int k = 0; k < 2; k++) {
            int c = c0 + ty + 8 * m;
            int b = b0 + tx + 32 * k;
            if (c < CC) g_Pc[c * BB + b] = psum(accA[m][k]) * psum(accB[m][k]);
        }
}

// ---------------- 6) generic A[M,K] @ B[K,300] --------------------------------
__global__ void gemm_rn_kernel(const float* __restrict__ slotp, int mode) {
    const float* A  = mode ? g_Pc : slotp;
    const float* Bm = mode ? g_fu : g_M1;
    float* Out      = mode ? g_mc : g_mr;
    int K           = mode ? BB : DD;

    __shared__ __align__(8) float As[64][32];
    __shared__ __align__(8) float Bs[128][34];
    int t = threadIdx.x, tx = t & 31, ty = t >> 5;
    int m0 = blockIdx.x * 64, n0 = blockIdx.y * 128;

    ull acc[8][4];
    #pragma unroll
    for (int m = 0; m < 8; m++)
        #pragma unroll
        for (int k = 0; k < 4; k++) acc[m][k] = 0ull;

    int nch = (K + 31) >> 5;
    for (int ch = 0; ch < nch; ch++) {
        int k0 = ch * 32;
        __syncthreads();
        #pragma unroll
        for (int i = 0; i < 8; i++) {
            int idx = t + i * 256;
            int row = idx >> 5, kk = idx & 31;
            int m = m0 + row, k = k0 + kk;
            As[row][kk] = (m < CC && k < K) ? A[m * K + k] : 0.f;
        }
        #pragma unroll
        for (int i = 0; i < 16; i++) {
            int idx = t + i * 256;
            int nn = idx & 127, kk = idx >> 7;
            int n = n0 + nn, k = k0 + kk;
            Bs[nn][kk] = (k < K && n < DD) ? Bm[k * DD + n] : 0.f;
        }
        __syncthreads();
        #pragma unroll
        for (int p = 0; p < 16; p++) {
            ull a2[8], w2[4];
            #pragma unroll
            for (int m = 0; m < 8; m++) a2[m] = ld2(&As[ty + 8 * m][2 * p]);
            #pragma unroll
            for (int k = 0; k < 4; k++) w2[k] = ld2(&Bs[tx + 32 * k][2 * p]);
            #pragma unroll
            for (int m = 0; m < 8; m++)
                #pragma unroll
                for (int k = 0; k < 4; k++) fma2(acc[m][k], a2[m], w2[k]);
        }
    }
    #pragma unroll
    for (int m = 0; m < 8; m++)
        #pragma unroll
        for (int k = 0; k < 4; k++) {
            int mm = m0 + ty + 8 * m;
            int n = tx + 32 * k + n0;
            if (mm < CC && n < DD) Out[mm * DD + n] = psum(acc[m][k]);
        }
}

// ---------------- 7) y2/y3 ----------------------------------------------------
__global__ void y23_kernel(const float* __restrict__ Wmr, const float* __restrict__ bmr,
                           const float* __restrict__ Wmc, const float* __restrict__ bmc,
                           const float* __restrict__ Wj,  const float* __restrict__ bj) {
    int which = blockIdx.y;
    const float* Min = which ? g_mc : g_mr;
    const float* Wm  = which ? Wmc : Wmr;
    const float* bm  = which ? bmc : bmr;

    __shared__ __align__(8) float As[32][32];
    __shared__ __align__(8) float Ws[128][34];
    __shared__ float bmS[128], WjS[128];
    int t = threadIdx.x, tx = t & 31, ty = t >> 5;
    int c0 = blockIdx.x * 32;
    if (t < 128) {
        bmS[t] = (t < HH) ? bm[t] : 0.f;
        WjS[t] = (t < HH) ? Wj[t] : 0.f;
    }

    ull acc[4][4];
    #pragma unroll
    for (int m = 0; m < 4; m++)
        #pragma unroll
        for (int k = 0; k < 4; k++) acc[m][k] = 0ull;

    for (int d0 = 0; d0 < DD; d0 += 32) {
        __syncthreads();
        #pragma unroll
        for (int i = 0; i < 4; i++) {
            int idx = t + i * 256;
            int row = idx >> 5, dd = idx & 31;
            int c = c0 + row, d = d0 + dd;
            As[row][dd] = (c < CC && d < DD) ? sigf(Min[c * DD + d]) : 0.f;
        }
        #pragma unroll
        for (int i = 0; i < 16; i++) {
            int idx = t + i * 256;
            int h = idx >> 5, dd = idx & 31;
            int d = d0 + dd;
            Ws[h][dd] = (h < HH && d < DD) ? Wm[h * DD + d] : 0.f;
        }
        __syncthreads();
        #pragma unroll
        for (int p = 0; p < 16; p++) {
            ull a2[4], w2[4];
            #pragma unroll
            for (int m = 0; m < 4; m++) a2[m] = ld2(&As[ty + 8 * m][2 * p]);
            #pragma unroll
            for (int k = 0; k < 4; k++) w2[k] = ld2(&Ws[tx + 32 * k][2 * p]);
            #pragma unroll
            for (int m = 0; m < 4; m++)
                #pragma unroll
                for (int k = 0; k < 4; k++) fma2(acc[m][k], a2[m], w2[k]);
        }
    }
    float bjv = bj[0];
    #pragma unroll
    for (int m = 0; m < 4; m++) {
        float pv = 0.f;
        #pragma unroll
        for (int k = 0; k < 4; k++) {
            int h = tx + 32 * k;
            float hid = psum(acc[m][k]) + bmS[h];
            pv += sigf(hid) * WjS[h];
        }
        pv = wredsum(pv);
        if (tx == 0) {
            int c = c0 + ty + 8 * m;
            if (c < CC) g_y23[which * CC + c] = pv + bjv;
        }
    }
}

// ---------------- 8) fused main (n-pair scheme, conflict-free) ----------------
// hidden[h][c] = sum_d sigf(cand_t[d][c]*fu[b][d]) * Wd_dup[d][h]
__global__ void __launch_bounds__(256) main_kernel(
        const float* __restrict__ bd, const float* __restrict__ Wj,
        const float* __restrict__ bj, const float* __restrict__ ypast,
        float* __restrict__ out) {
    __shared__ __align__(16) ull  WsD[16][128];   // dup Wd pairs [kk][h]
    __shared__ __align__(16) float Act[16][130];  // activation [kk][cc] (c contiguous)
    __shared__ float fuS[304];
    __shared__ float bdS[128], WjS[128];
    __shared__ __align__(16) float red[8][130];

    int t = threadIdx.x, tx = t & 31, ty = t >> 5;
    int c0 = blockIdx.x * 128;
    int b  = blockIdx.y;

    if (t < 128) {
        bdS[t] = (t < HH) ? bd[t] : 0.f;
        WjS[t] = (t < HH) ? Wj[t] : 0.f;
    }
    for (int i = t; i < DD; i += 256) fuS[i] = g_fu[b * DD + i];

    ull acc[16][2];
    #pragma unroll
    for (int m = 0; m < 16; m++) { acc[m][0] = 0ull; acc[m][1] = 0ull; }

    for (int ch = 0; ch < 19; ch++) {
        int d0 = ch * 16;
        __syncthreads();
        #pragma unroll
        for (int i = 0; i < 8; i++) {       // WsD: 2048 ull
            int idx = t + i * 256;
            int row = idx >> 7, col = idx & 127;
            WsD[row][col] = g_Wd_dup[(d0 + row) * 128 + col];
        }
        #pragma unroll
        for (int i = 0; i < 8; i++) {       // Act: 2048 floats
            int idx = t + i * 256;
            int kk = idx >> 7, cc = idx & 127;
            int d = d0 + kk, c = c0 + cc;
            float v = 0.f;
            if (d < DD && c < CC) v = sigf(g_cand_t[d * CC + c] * fuS[d]);
            Act[kk][cc] = v;
        }
        __syncthreads();
        #pragma unroll
        for (int kk = 0; kk < 16; kk++) {
            ull b0v = ld2(&Act[kk][2 * tx]);
            ull b1v = ld2(&Act[kk][2 * tx + 64]);
            #pragma unroll
            for (int mp = 0; mp < 8; mp++) {
                ulonglong2 a = *reinterpret_cast<const ulonglong2*>(&WsD[kk][16 * ty + 2 * mp]);
                fma2(acc[2 * mp][0], a.x, b0v);
                fma2(acc[2 * mp][1], a.x, b1v);
                fma2(acc[2 * mp + 1][0], a.y, b0v);
                fma2(acc[2 * mp + 1][1], a.y, b1v);
            }
        }
    }

    // per-thread partial of y1 over its 16 h values, for its 4 c columns
    float p00 = 0.f, p01 = 0.f, p10 = 0.f, p11 = 0.f;
    #pragma unroll
    for (int m = 0; m < 16; m++) {
        int h = 16 * ty + m;
        float bdv = bdS[h], wjv = WjS[h];
        p00 += sigf(lo2(acc[m][0]) + bdv) * wjv;
        p01 += sigf(hi2(acc[m][0]) + bdv) * wjv;
        p10 += sigf(lo2(acc[m][1]) + bdv) * wjv;
        p11 += sigf(hi2(acc[m][1]) + bdv) * wjv;
    }
    __syncthreads();
    *reinterpret_cast<float2*>(&red[ty][2 * tx])      = make_float2(p00, p01);
    *reinterpret_cast<float2*>(&red[ty][2 * tx + 64]) = make_float2(p10, p11);
    __syncthreads();

    if (t < 128) {
        int c = c0 + t;
        if (c < CC) {
            float s = 0.f;
            #pragma unroll
            for (int w = 0; w < 8; w++) s += red[w][t];
            float y1 = s + bj[0];
            float v = 0.5f * (y1 + g_y23[c] + g_y23[CC + c]) + 0.5f * ypast[b * CC + c];
            out[b * CC + c] = v;
        }
    }
}

// ---------------- launch ------------------------------------------------------
extern "C" void kernel_launch(void* const* d_in, const int* in_sizes, int n_in,
                              void* d_out, int out_size) {
    const float* utt   = (const float*)d_in[0];
    const float* sys   = (const float*)d_in[1];
    const float* cs    = (const float*)d_in[2];
    const float* cv    = (const float*)d_in[3];
    const float* ypast = (const float*)d_in[4];
    const float* slot  = (const float*)d_in[5];
    const float* val   = (const float*)d_in[6];
    const float* Wc    = (const float*)d_in[7];
    const float* bc    = (const float*)d_in[8];
    const float* w1    = (const float*)d_in[9];
    const float* b1    = (const float*)d_in[10];
    const float* w2    = (const float*)d_in[11];
    const float* b2    = (const float*)d_in[12];
    const float* w3    = (const float*)d_in[13];
    const float* b3    = (const float*)d_in[14];
    const float* Wd    = (const float*)d_in[15];
    const float* bd    = (const float*)d_in[16];
    const float* Wmr   = (const float*)d_in[17];
    const float* bmr   = (const float*)d_in[18];
    const float* Wmc   = (const float*)d_in[19];
    const float* bmc   = (const float*)d_in[20];
    const float* Wj    = (const float*)d_in[21];
    const float* bj    = (const float*)d_in[22];
    float* out = (float*)d_out;

    int nrep = (N_WT + N_WD + N_M1 + 255) / 256;
    repack_kernel<<<nrep, 256>>>(w1, w2, w3, Wd);
    conv_kernel<<<dim3(5, BB), 256>>>(utt, b1, b2, b3);
    cand_kernel<<<dim3(63, 3), 256>>>(slot, val, Wc, bc);
    m1_kernel<<<dim3(3, 75, 4), 128>>>(sys);
    pc_kernel<<<dim3(16, 2), 256>>>(slot, val, cs, cv);
    gemm_rn_kernel<<<dim3(16, 3), 256>>>(slot, 0);   // m_r = slot @ M1
    gemm_rn_kernel<<<dim3(16, 3), 256>>>(slot, 1);   // m_c = P_c @ fu
    y23_kernel<<<dim3(32, 2), 256>>>(Wmr, bmr, Wmc, bmc, Wj, bj);
    main_kernel<<<dim3(8, BB), 256>>>(bd, Wj, bj, ypast, out);
}